// round 1
// baseline (speedup 1.0000x reference)
#include <cuda_runtime.h>

// DiffJPEG: per 8x8 block  D @ X @ D^T  -> round(./Q)*Q -> D^T @ . @ D
// One thread per 8x8 block, everything in registers, DCT matrix as
// compile-time immediates so ptxas emits FFMA-imm (no operand loads).

namespace {

// 8-point DCT-II matrix, c0=sqrt(1/8), ci=0.5, D[i][j]=ci*cos((2j+1)*i*pi/16)
__device__ constexpr float Dm[8][8] = {
    { 0.35355339059327373f,  0.35355339059327373f,  0.35355339059327373f,  0.35355339059327373f,
      0.35355339059327373f,  0.35355339059327373f,  0.35355339059327373f,  0.35355339059327373f },
    { 0.49039264020161522f,  0.41573480615127262f,  0.27778511650980114f,  0.09754516100806412f,
     -0.09754516100806412f, -0.27778511650980114f, -0.41573480615127262f, -0.49039264020161522f },
    { 0.46193976625564337f,  0.19134171618254492f, -0.19134171618254492f, -0.46193976625564337f,
     -0.46193976625564337f, -0.19134171618254492f,  0.19134171618254492f,  0.46193976625564337f },
    { 0.41573480615127262f, -0.09754516100806412f, -0.49039264020161522f, -0.27778511650980114f,
      0.27778511650980114f,  0.49039264020161522f,  0.09754516100806412f, -0.41573480615127262f },
    { 0.35355339059327373f, -0.35355339059327373f, -0.35355339059327373f,  0.35355339059327373f,
      0.35355339059327373f, -0.35355339059327373f, -0.35355339059327373f,  0.35355339059327373f },
    { 0.27778511650980114f, -0.49039264020161522f,  0.09754516100806412f,  0.41573480615127262f,
     -0.41573480615127262f, -0.09754516100806412f,  0.49039264020161522f, -0.27778511650980114f },
    { 0.19134171618254492f, -0.46193976625564337f,  0.46193976625564337f, -0.19134171618254492f,
     -0.19134171618254492f,  0.46193976625564337f, -0.46193976625564337f,  0.19134171618254492f },
    { 0.09754516100806412f, -0.27778511650980114f,  0.41573480615127262f, -0.49039264020161522f,
      0.49039264020161522f, -0.41573480615127262f,  0.27778511650980114f, -0.09754516100806412f }
};

// quality=50 -> scale=100 -> Q = floor((q*100+50)/100) = q (integers), max(.,1)=q
__device__ constexpr float Qm[8][8] = {
    {16.f, 11.f, 10.f, 16.f, 24.f, 40.f, 51.f, 61.f},
    {12.f, 12.f, 14.f, 19.f, 26.f, 58.f, 60.f, 55.f},
    {14.f, 13.f, 16.f, 24.f, 40.f, 57.f, 69.f, 56.f},
    {14.f, 17.f, 22.f, 29.f, 51.f, 87.f, 80.f, 62.f},
    {18.f, 22.f, 37.f, 56.f, 68.f, 109.f, 103.f, 77.f},
    {24.f, 35.f, 55.f, 64.f, 81.f, 104.f, 113.f, 92.f},
    {49.f, 64.f, 78.f, 87.f, 103.f, 121.f, 120.f, 101.f},
    {72.f, 92.f, 95.f, 98.f, 112.f, 100.f, 103.f, 99.f}
};

__device__ constexpr float Qinv[8][8] = {
    {1.f/16.f, 1.f/11.f, 1.f/10.f, 1.f/16.f, 1.f/24.f, 1.f/40.f, 1.f/51.f, 1.f/61.f},
    {1.f/12.f, 1.f/12.f, 1.f/14.f, 1.f/19.f, 1.f/26.f, 1.f/58.f, 1.f/60.f, 1.f/55.f},
    {1.f/14.f, 1.f/13.f, 1.f/16.f, 1.f/24.f, 1.f/40.f, 1.f/57.f, 1.f/69.f, 1.f/56.f},
    {1.f/14.f, 1.f/17.f, 1.f/22.f, 1.f/29.f, 1.f/51.f, 1.f/87.f, 1.f/80.f, 1.f/62.f},
    {1.f/18.f, 1.f/22.f, 1.f/37.f, 1.f/56.f, 1.f/68.f, 1.f/109.f, 1.f/103.f, 1.f/77.f},
    {1.f/24.f, 1.f/35.f, 1.f/55.f, 1.f/64.f, 1.f/81.f, 1.f/104.f, 1.f/113.f, 1.f/92.f},
    {1.f/49.f, 1.f/64.f, 1.f/78.f, 1.f/87.f, 1.f/103.f, 1.f/121.f, 1.f/120.f, 1.f/101.f},
    {1.f/72.f, 1.f/92.f, 1.f/95.f, 1.f/98.f, 1.f/112.f, 1.f/100.f, 1.f/103.f, 1.f/99.f}
};

constexpr int W = 512;        // image width/height
constexpr int BLK_X = 64;     // 512/8 blocks per row
constexpr int N_THREADS_TOTAL = 32 * 3 * 64 * 64;  // one thread per 8x8 block

} // namespace

__global__ void __launch_bounds__(256)
diffjpeg_kernel(const float* __restrict__ in, float* __restrict__ out) {
    const int t = blockIdx.x * 256 + threadIdx.x;
    const int bx = t & (BLK_X - 1);
    const int by = (t >> 6) & (BLK_X - 1);
    const int bc = t >> 12;   // fused batch*channel index, 0..95

    const size_t off = ((size_t)bc * W + (size_t)by * 8) * W + (size_t)bx * 8;
    const float* __restrict__ p = in + off;

    float X[8][8];

    // ---- load 8x8 block, 2x float4 per row, front-batched for MLP ----
#pragma unroll
    for (int r = 0; r < 8; ++r) {
        float4 a = __ldg((const float4*)(p + (size_t)r * W));
        float4 b = __ldg((const float4*)(p + (size_t)r * W + 4));
        X[r][0] = a.x; X[r][1] = a.y; X[r][2] = a.z; X[r][3] = a.w;
        X[r][4] = b.x; X[r][5] = b.y; X[r][6] = b.z; X[r][7] = b.w;
    }

    // ---- stage 1: X <- X @ D^T  (row transform) ----
#pragma unroll
    for (int r = 0; r < 8; ++r) {
        float tv[8];
#pragma unroll
        for (int j = 0; j < 8; ++j) {
            float acc = X[r][0] * Dm[j][0];
#pragma unroll
            for (int k = 1; k < 8; ++k) acc = fmaf(X[r][k], Dm[j][k], acc);
            tv[j] = acc;
        }
#pragma unroll
        for (int j = 0; j < 8; ++j) X[r][j] = tv[j];
    }

    // ---- stage 2: X <- D @ X  (column transform) ----
#pragma unroll
    for (int c = 0; c < 8; ++c) {
        float tv[8];
#pragma unroll
        for (int i = 0; i < 8; ++i) {
            float acc = Dm[i][0] * X[0][c];
#pragma unroll
            for (int k = 1; k < 8; ++k) acc = fmaf(Dm[i][k], X[k][c], acc);
            tv[i] = acc;
        }
#pragma unroll
        for (int i = 0; i < 8; ++i) X[i][c] = tv[i];
    }

    // ---- quantize / dequantize: round half-to-even, matches jnp.round ----
#pragma unroll
    for (int i = 0; i < 8; ++i)
#pragma unroll
        for (int j = 0; j < 8; ++j)
            X[i][j] = rintf(X[i][j] * Qinv[i][j]) * Qm[i][j];

    // ---- stage 3: X <- D^T @ X  (column transform with transposed D) ----
#pragma unroll
    for (int c = 0; c < 8; ++c) {
        float tv[8];
#pragma unroll
        for (int i = 0; i < 8; ++i) {
            float acc = Dm[0][i] * X[0][c];
#pragma unroll
            for (int k = 1; k < 8; ++k) acc = fmaf(Dm[k][i], X[k][c], acc);
            tv[i] = acc;
        }
#pragma unroll
        for (int i = 0; i < 8; ++i) X[i][c] = tv[i];
    }

    // ---- stage 4: X <- X @ D  (row transform) ----
#pragma unroll
    for (int r = 0; r < 8; ++r) {
        float tv[8];
#pragma unroll
        for (int j = 0; j < 8; ++j) {
            float acc = X[r][0] * Dm[0][j];
#pragma unroll
            for (int k = 1; k < 8; ++k) acc = fmaf(X[r][k], Dm[k][j], acc);
            tv[j] = acc;
        }
#pragma unroll
        for (int j = 0; j < 8; ++j) X[r][j] = tv[j];
    }

    // ---- store ----
    float* __restrict__ q = out + off;
#pragma unroll
    for (int r = 0; r < 8; ++r) {
        *(float4*)(q + (size_t)r * W)     = make_float4(X[r][0], X[r][1], X[r][2], X[r][3]);
        *(float4*)(q + (size_t)r * W + 4) = make_float4(X[r][4], X[r][5], X[r][6], X[r][7]);
    }
}

extern "C" void kernel_launch(void* const* d_in, const int* in_sizes, int n_in,
                              void* d_out, int out_size) {
    const float* img = (const float*)d_in[0];
    float* out = (float*)d_out;
    (void)in_sizes; (void)n_in; (void)out_size;

    const int threads = 256;
    const int blocks = N_THREADS_TOTAL / threads;  // 1536
    diffjpeg_kernel<<<blocks, threads>>>(img, out);
}

// round 2
// speedup vs baseline: 1.0910x; 1.0910x over previous
#include <cuda_runtime.h>

// DiffJPEG: per 8x8 block  D @ X @ D^T  -> round(./Q)*Q -> D^T @ . @ D
// One thread per 8x8 block, all in registers.
// R2: even/odd DCT folding (40 ops per 1-D transform instead of 64) and
// magic-constant round-to-nearest-even instead of FRND.

namespace {

// 8-point DCT-II matrix, c0=sqrt(1/8), ci=0.5, D[i][j]=ci*cos((2j+1)*i*pi/16)
__device__ constexpr float Dm[8][8] = {
    { 0.35355339059327373f,  0.35355339059327373f,  0.35355339059327373f,  0.35355339059327373f,
      0.35355339059327373f,  0.35355339059327373f,  0.35355339059327373f,  0.35355339059327373f },
    { 0.49039264020161522f,  0.41573480615127262f,  0.27778511650980114f,  0.09754516100806412f,
     -0.09754516100806412f, -0.27778511650980114f, -0.41573480615127262f, -0.49039264020161522f },
    { 0.46193976625564337f,  0.19134171618254492f, -0.19134171618254492f, -0.46193976625564337f,
     -0.46193976625564337f, -0.19134171618254492f,  0.19134171618254492f,  0.46193976625564337f },
    { 0.41573480615127262f, -0.09754516100806412f, -0.49039264020161522f, -0.27778511650980114f,
      0.27778511650980114f,  0.49039264020161522f,  0.09754516100806412f, -0.41573480615127262f },
    { 0.35355339059327373f, -0.35355339059327373f, -0.35355339059327373f,  0.35355339059327373f,
      0.35355339059327373f, -0.35355339059327373f, -0.35355339059327373f,  0.35355339059327373f },
    { 0.27778511650980114f, -0.49039264020161522f,  0.09754516100806412f,  0.41573480615127262f,
     -0.41573480615127262f, -0.09754516100806412f,  0.49039264020161522f, -0.27778511650980114f },
    { 0.19134171618254492f, -0.46193976625564337f,  0.46193976625564337f, -0.19134171618254492f,
     -0.19134171618254492f,  0.46193976625564337f, -0.46193976625564337f,  0.19134171618254492f },
    { 0.09754516100806412f, -0.27778511650980114f,  0.41573480615127262f, -0.49039264020161522f,
      0.49039264020161522f, -0.41573480615127262f,  0.27778511650980114f, -0.09754516100806412f }
};

// quality=50 -> scale=100 -> Q = q_luma exactly (integers)
__device__ constexpr float Qm[8][8] = {
    {16.f, 11.f, 10.f, 16.f, 24.f, 40.f, 51.f, 61.f},
    {12.f, 12.f, 14.f, 19.f, 26.f, 58.f, 60.f, 55.f},
    {14.f, 13.f, 16.f, 24.f, 40.f, 57.f, 69.f, 56.f},
    {14.f, 17.f, 22.f, 29.f, 51.f, 87.f, 80.f, 62.f},
    {18.f, 22.f, 37.f, 56.f, 68.f, 109.f, 103.f, 77.f},
    {24.f, 35.f, 55.f, 64.f, 81.f, 104.f, 113.f, 92.f},
    {49.f, 64.f, 78.f, 87.f, 103.f, 121.f, 120.f, 101.f},
    {72.f, 92.f, 95.f, 98.f, 112.f, 100.f, 103.f, 99.f}
};

__device__ constexpr float Qinv[8][8] = {
    {1.f/16.f, 1.f/11.f, 1.f/10.f, 1.f/16.f, 1.f/24.f, 1.f/40.f, 1.f/51.f, 1.f/61.f},
    {1.f/12.f, 1.f/12.f, 1.f/14.f, 1.f/19.f, 1.f/26.f, 1.f/58.f, 1.f/60.f, 1.f/55.f},
    {1.f/14.f, 1.f/13.f, 1.f/16.f, 1.f/24.f, 1.f/40.f, 1.f/57.f, 1.f/69.f, 1.f/56.f},
    {1.f/14.f, 1.f/17.f, 1.f/22.f, 1.f/29.f, 1.f/51.f, 1.f/87.f, 1.f/80.f, 1.f/62.f},
    {1.f/18.f, 1.f/22.f, 1.f/37.f, 1.f/56.f, 1.f/68.f, 1.f/109.f, 1.f/103.f, 1.f/77.f},
    {1.f/24.f, 1.f/35.f, 1.f/55.f, 1.f/64.f, 1.f/81.f, 1.f/104.f, 1.f/113.f, 1.f/92.f},
    {1.f/49.f, 1.f/64.f, 1.f/78.f, 1.f/87.f, 1.f/103.f, 1.f/121.f, 1.f/120.f, 1.f/101.f},
    {1.f/72.f, 1.f/92.f, 1.f/95.f, 1.f/98.f, 1.f/112.f, 1.f/100.f, 1.f/103.f, 1.f/99.f}
};

constexpr int W = 512;
constexpr int BLK_X = 64;
constexpr int N_THREADS_TOTAL = 32 * 3 * 64 * 64;
constexpr float RNDC = 12582912.0f;  // 1.5 * 2^23, round-to-nearest-even magic

// Forward 8-point DCT-II, in place, stride S.
// y[2m]   = sum_k D[2m][k]   * (x[k]+x[7-k])   (symmetric rows)
// y[2m+1] = sum_k D[2m+1][k] * (x[k]-x[7-k])   (antisymmetric rows)
template<int S>
__device__ __forceinline__ void fwd8(float* __restrict__ v) {
    float s[4], d[4];
#pragma unroll
    for (int k = 0; k < 4; ++k) {
        s[k] = v[k * S] + v[(7 - k) * S];
        d[k] = v[k * S] - v[(7 - k) * S];
    }
#pragma unroll
    for (int m = 0; m < 4; ++m) {
        float a = Dm[2 * m][0] * s[0];
        float b = Dm[2 * m + 1][0] * d[0];
#pragma unroll
        for (int k = 1; k < 4; ++k) {
            a = fmaf(Dm[2 * m][k], s[k], a);
            b = fmaf(Dm[2 * m + 1][k], d[k], b);
        }
        v[(2 * m) * S] = a;
        v[(2 * m + 1) * S] = b;
    }
}

// Inverse 8-point (DCT-III), in place, stride S.
// y[j] = sum_i D[i][j] u[i];  even-i part E is symmetric in j,
// odd-i part O antisymmetric:  y[j]=E[j]+O[j], y[7-j]=E[j]-O[j].
template<int S>
__device__ __forceinline__ void inv8(float* __restrict__ v) {
    float E[4], O[4];
#pragma unroll
    for (int j = 0; j < 4; ++j) {
        float e = Dm[0][j] * v[0];
        float o = Dm[1][j] * v[S];
#pragma unroll
        for (int m = 1; m < 4; ++m) {
            e = fmaf(Dm[2 * m][j], v[(2 * m) * S], e);
            o = fmaf(Dm[2 * m + 1][j], v[(2 * m + 1) * S], o);
        }
        E[j] = e;
        O[j] = o;
    }
#pragma unroll
    for (int j = 0; j < 4; ++j) {
        v[j * S] = E[j] + O[j];
        v[(7 - j) * S] = E[j] - O[j];
    }
}

} // namespace

__global__ void __launch_bounds__(256)
diffjpeg_kernel(const float* __restrict__ in, float* __restrict__ out) {
    const int t = blockIdx.x * 256 + threadIdx.x;
    const int bx = t & (BLK_X - 1);
    const int by = (t >> 6) & (BLK_X - 1);
    const int bc = t >> 12;   // fused batch*channel index, 0..95

    const size_t off = ((size_t)bc * W + (size_t)by * 8) * W + (size_t)bx * 8;
    const float* __restrict__ p = in + off;

    float X[64];

    // ---- load 8x8 block, 2x float4 per row, front-batched for MLP ----
#pragma unroll
    for (int r = 0; r < 8; ++r) {
        float4 a = __ldg((const float4*)(p + (size_t)r * W));
        float4 b = __ldg((const float4*)(p + (size_t)r * W + 4));
        X[r * 8 + 0] = a.x; X[r * 8 + 1] = a.y; X[r * 8 + 2] = a.z; X[r * 8 + 3] = a.w;
        X[r * 8 + 4] = b.x; X[r * 8 + 5] = b.y; X[r * 8 + 6] = b.z; X[r * 8 + 7] = b.w;
    }

    // ---- forward DCT: rows then columns ----
#pragma unroll
    for (int r = 0; r < 8; ++r) fwd8<1>(X + r * 8);
#pragma unroll
    for (int c = 0; c < 8; ++c) fwd8<8>(X + c);

    // ---- quantize/dequantize: round-to-nearest-even via magic constant ----
#pragma unroll
    for (int i = 0; i < 8; ++i)
#pragma unroll
        for (int j = 0; j < 8; ++j) {
            float rbits = __fadd_rn(__fmaf_rn(X[i * 8 + j], Qinv[i][j], RNDC), -RNDC);
            X[i * 8 + j] = rbits * Qm[i][j];
        }

    // ---- inverse DCT: columns then rows ----
#pragma unroll
    for (int c = 0; c < 8; ++c) inv8<8>(X + c);
#pragma unroll
    for (int r = 0; r < 8; ++r) inv8<1>(X + r * 8);

    // ---- store ----
    float* __restrict__ q = out + off;
#pragma unroll
    for (int r = 0; r < 8; ++r) {
        *(float4*)(q + (size_t)r * W) =
            make_float4(X[r * 8 + 0], X[r * 8 + 1], X[r * 8 + 2], X[r * 8 + 3]);
        *(float4*)(q + (size_t)r * W + 4) =
            make_float4(X[r * 8 + 4], X[r * 8 + 5], X[r * 8 + 6], X[r * 8 + 7]);
    }
}

extern "C" void kernel_launch(void* const* d_in, const int* in_sizes, int n_in,
                              void* d_out, int out_size) {
    const float* img = (const float*)d_in[0];
    float* out = (float*)d_out;
    (void)in_sizes; (void)n_in; (void)out_size;

    const int threads = 256;
    const int blocks = N_THREADS_TOTAL / threads;  // 1536
    diffjpeg_kernel<<<blocks, threads>>>(img, out);
}